// round 5
// baseline (speedup 1.0000x reference)
#include <cuda_runtime.h>
#include <cstdint>

#define NN 50000
#define NE_IN 800000
#define NE (NE_IN + NN)
#define DD 128
#define NG 64
#define NC 10
#define NL 5

#define SCAN_BLOCKS ((NN + 1023) / 1024)

// ---------------- static device scratch ----------------
__device__ __align__(16) float g_bufA[NN * DD];
__device__ __align__(16) float g_bufB[NN * DD];
__device__ __align__(16) float g_xl[NN * DD];
__device__ __align__(16) float g_xr[NN * DD];
__device__ __align__(16) float g_Wpack[NL * DD * 256];
__device__ __align__(16) float g_bpack[NL * 256];
__device__ int   g_rowptr[NN + 1];
__device__ int   g_cursor[NN];
__device__ int   g_esrc[NE];
__device__ int   g_cnt[NN];
__device__ int   g_bsum[64];
__device__ __align__(16) float g_pool[NG * DD];
__device__ float g_pcnt[NG];

__device__ __forceinline__ uint32_t f2tf32(float f) {
    uint32_t u;
    asm volatile("cvt.rna.tf32.f32 %0, %1;" : "=r"(u) : "f"(f));
    return u;
}
__device__ __forceinline__ float f2tf32f(float f) {
    uint32_t u = f2tf32(f);
    return __uint_as_float(u);
}

// ---------------- init ----------------
__global__ void init_kernel() {
    int i = blockIdx.x * blockDim.x + threadIdx.x;
    if (i < NN) g_cnt[i] = 0;
    if (i < NG * DD) g_pool[i] = 0.f;
    if (i < NG) g_pcnt[i] = 0.f;
}

// ---------------- round x (layer-0 input) into g_bufB as tf32 ----------------
__global__ void roundx_kernel(const float* __restrict__ x) {
    int i = blockIdx.x * blockDim.x + threadIdx.x;
    if (i < NN * DD / 4) {
        float4 v = ((const float4*)x)[i];
        v.x = f2tf32f(v.x); v.y = f2tf32f(v.y);
        v.z = f2tf32f(v.z); v.w = f2tf32f(v.w);
        ((float4*)g_bufB)[i] = v;
    }
}

// ---------------- CSR build ----------------
__global__ void count_kernel(const int* __restrict__ ei) {
    int e = blockIdx.x * blockDim.x + threadIdx.x;
    if (e >= NE) return;
    int d = (e < NE_IN) ? ei[NE_IN + e] : (e - NE_IN);
    atomicAdd(&g_cnt[d], 1);
}

__global__ void scan1_kernel() {
    __shared__ int wsum[32];
    int tid = threadIdx.x;
    int i = blockIdx.x * 1024 + tid;
    int v = (i < NN) ? g_cnt[i] : 0;
    int x = v;
#pragma unroll
    for (int off = 1; off < 32; off <<= 1) {
        int y = __shfl_up_sync(0xffffffffu, x, off);
        if ((tid & 31) >= off) x += y;
    }
    if ((tid & 31) == 31) wsum[tid >> 5] = x;
    __syncthreads();
    if (tid < 32) {
        int w = wsum[tid];
        int xs = w;
#pragma unroll
        for (int off = 1; off < 32; off <<= 1) {
            int y = __shfl_up_sync(0xffffffffu, xs, off);
            if (tid >= off) xs += y;
        }
        wsum[tid] = xs - w;
    }
    __syncthreads();
    int incl = x + wsum[tid >> 5];
    if (i < NN) g_rowptr[i] = incl - v;
    if (tid == 1023) g_bsum[blockIdx.x] = incl;
}

__global__ void scan2_kernel() {
    if (threadIdx.x == 0) {
        int acc = 0;
        for (int b = 0; b < SCAN_BLOCKS; b++) { int t = g_bsum[b]; g_bsum[b] = acc; acc += t; }
    }
}

__global__ void scan3_kernel() {
    int i = blockIdx.x * 1024 + threadIdx.x;
    if (i < NN) {
        int r = g_rowptr[i] + g_bsum[blockIdx.x];
        g_rowptr[i] = r;
        g_cursor[i] = r;
    }
    if (i == 0) g_rowptr[NN] = NE;
}

__global__ void scatter_kernel(const int* __restrict__ ei) {
    int e = blockIdx.x * blockDim.x + threadIdx.x;
    if (e >= NE) return;
    int s, d;
    if (e < NE_IN) { s = ei[e]; d = ei[NE_IN + e]; }
    else           { s = e - NE_IN; d = s; }
    int pos = atomicAdd(&g_cursor[d], 1);
    g_esrc[pos] = s;
}

// ---------------- pack weights (tf32-rounded) ----------------
__global__ void pack_kernel(const float* __restrict__ Wl, const float* __restrict__ bl,
                            const float* __restrict__ Wr, const float* __restrict__ br) {
    int i = blockIdx.x * blockDim.x + threadIdx.x;
    int WTOT = NL * DD * 256;
    if (i < WTOT) {
        int l = i / (DD * 256);
        int rem = i - l * DD * 256;
        int k = rem >> 8, j = rem & 255;
        float w = (j < DD) ? Wl[(l * DD + k) * DD + j]
                           : Wr[(l * DD + k) * DD + (j - DD)];
        g_Wpack[i] = f2tf32f(w);
    } else if (i < WTOT + NL * 256) {
        int r = i - WTOT;
        int l = r >> 8, j = r & 255;
        g_bpack[r] = (j < DD) ? bl[l * DD + j] : br[l * DD + j - DD];
    }
}

// ---------------- tf32 tensor-core GEMM (operands pre-rounded) ----------------
#define GBM 128
#define GBN 64
#define GBK 16

__device__ __forceinline__ void cpa16(void* smem, const void* g) {
    unsigned sa = (unsigned)__cvta_generic_to_shared(smem);
    asm volatile("cp.async.cg.shared.global [%0], [%1], 16;" :: "r"(sa), "l"(g));
}
__device__ __forceinline__ void mma8(float* c, const uint32_t* a, const uint32_t* b) {
    asm volatile(
        "mma.sync.aligned.m16n8k8.row.col.f32.tf32.tf32.f32 "
        "{%0,%1,%2,%3},{%4,%5,%6,%7},{%8,%9},{%0,%1,%2,%3};"
        : "+f"(c[0]), "+f"(c[1]), "+f"(c[2]), "+f"(c[3])
        : "r"(a[0]), "r"(a[1]), "r"(a[2]), "r"(a[3]), "r"(b[0]), "r"(b[1]));
}

__global__ __launch_bounds__(256) void gemm_tc_kernel(int l) {
    const float* A = (l & 1) ? g_bufA : g_bufB;   // l=0 reads pre-rounded x in bufB
    __shared__ float As[2][GBM][GBK + 4];
    __shared__ float Bs[2][GBK][GBN + 4];

    int tid  = threadIdx.x;
    int lane = tid & 31;
    int warp = tid >> 5;
    int wm = warp >> 1, wn = warp & 1;
    int g = lane >> 2, t = lane & 3;
    int bm0 = blockIdx.x * GBM;

    const float* Wb = g_Wpack + l * (DD * 256) + blockIdx.y * GBN;

    float acc[2][4][4];
#pragma unroll
    for (int mt = 0; mt < 2; mt++)
#pragma unroll
        for (int nt = 0; nt < 4; nt++)
#pragma unroll
            for (int c = 0; c < 4; c++) acc[mt][nt][c] = 0.f;

    auto load_stage = [&](int buf, int k0) {
#pragma unroll
        for (int i = 0; i < 2; i++) {
            int idx = tid + i * 256;
            int row = idx >> 2, q = idx & 3;
            int gr = bm0 + row; if (gr >= NN) gr = NN - 1;
            cpa16(&As[buf][row][q * 4], A + (size_t)gr * DD + k0 + q * 4);
        }
        {
            int row = tid >> 4, q = tid & 15;
            cpa16(&Bs[buf][row][q * 4], Wb + (k0 + row) * 256 + q * 4);
        }
        asm volatile("cp.async.commit_group;");
    };

    load_stage(0, 0);

    int buf = 0;
#pragma unroll
    for (int kt = 0; kt < DD / GBK; kt++) {
        if (kt + 1 < DD / GBK) {
            load_stage(buf ^ 1, (kt + 1) * GBK);
            asm volatile("cp.async.wait_group 1;");
        } else {
            asm volatile("cp.async.wait_group 0;");
        }
        __syncthreads();

#pragma unroll
        for (int ks = 0; ks < 2; ks++) {
            int kk = ks * 8;
            uint32_t af[2][4];
#pragma unroll
            for (int mt = 0; mt < 2; mt++) {
                int r0 = wm * 32 + mt * 16 + g;
                af[mt][0] = *(const uint32_t*)&As[buf][r0][kk + t];
                af[mt][1] = *(const uint32_t*)&As[buf][r0 + 8][kk + t];
                af[mt][2] = *(const uint32_t*)&As[buf][r0][kk + t + 4];
                af[mt][3] = *(const uint32_t*)&As[buf][r0 + 8][kk + t + 4];
            }
            uint32_t bf[4][2];
#pragma unroll
            for (int nt = 0; nt < 4; nt++) {
                int c0 = wn * 32 + nt * 8 + g;
                bf[nt][0] = *(const uint32_t*)&Bs[buf][kk + t][c0];
                bf[nt][1] = *(const uint32_t*)&Bs[buf][kk + t + 4][c0];
            }
#pragma unroll
            for (int mt = 0; mt < 2; mt++)
#pragma unroll
                for (int nt = 0; nt < 4; nt++)
                    mma8(acc[mt][nt], af[mt], bf[nt]);
        }
        __syncthreads();
        buf ^= 1;
    }

    int cbase = blockIdx.y * GBN + wn * 32;
    const float* bp = g_bpack + l * 256;
    float* obase = (blockIdx.y < 2) ? g_xl : g_xr;
    int coff = (blockIdx.y < 2) ? cbase : cbase - DD;
#pragma unroll
    for (int mt = 0; mt < 2; mt++) {
        int r0 = bm0 + wm * 32 + mt * 16 + g;
#pragma unroll
        for (int nt = 0; nt < 4; nt++) {
            int cb = cbase + nt * 8 + 2 * t;
            int c  = coff + nt * 8 + 2 * t;
            float bx = bp[cb], by = bp[cb + 1];
            if (r0 < NN) {
                float2 v = make_float2(acc[mt][nt][0] + bx, acc[mt][nt][1] + by);
                *(float2*)(obase + (size_t)r0 * DD + c) = v;
            }
            if (r0 + 8 < NN) {
                float2 v = make_float2(acc[mt][nt][2] + bx, acc[mt][nt][3] + by);
                *(float2*)(obase + (size_t)(r0 + 8) * DD + c) = v;
            }
        }
    }
}

// ---------------- GAT edge aggregation ----------------
// one warp per dst node; lane = slot(lane>>3)*8 + head(lane&7)
// 8 edges per warp-iteration (2 per lane) for doubled gather MLP
__device__ __forceinline__ float lrl(float z) { return z > 0.f ? z : 0.2f * z; }

__global__ __launch_bounds__(256) void gat_kernel(const float* __restrict__ attb,
                                                  const float* __restrict__ biasb,
                                                  int outbuf, int round_out) {
    int gw = (blockIdx.x * blockDim.x + threadIdx.x) >> 5;
    int lane = threadIdx.x & 31;
    if (gw >= NN) return;
    float* hout = (outbuf == 0) ? g_bufA : g_bufB;

    int slot = lane >> 3, h = lane & 7;
    const float4* ap = (const float4*)(attb + h * 16);
    float4 at0 = ap[0], at1 = ap[1], at2 = ap[2], at3 = ap[3];
    const float4* xp = (const float4*)(g_xr + (size_t)gw * DD + h * 16);
    float4 xr0 = xp[0], xr1 = xp[1], xr2 = xp[2], xr3 = xp[3];

    int jb = g_rowptr[gw], je = g_rowptr[gw + 1];

#define DOT16(dst, p0, p1, p2, p3)                                             \
    {                                                                          \
        float dd_ = 0.f;                                                       \
        dd_ += at0.x * lrl(p0.x + xr0.x); dd_ += at0.y * lrl(p0.y + xr0.y);    \
        dd_ += at0.z * lrl(p0.z + xr0.z); dd_ += at0.w * lrl(p0.w + xr0.w);    \
        dd_ += at1.x * lrl(p1.x + xr1.x); dd_ += at1.y * lrl(p1.y + xr1.y);    \
        dd_ += at1.z * lrl(p1.z + xr1.z); dd_ += at1.w * lrl(p1.w + xr1.w);    \
        dd_ += at2.x * lrl(p2.x + xr2.x); dd_ += at2.y * lrl(p2.y + xr2.y);    \
        dd_ += at2.z * lrl(p2.z + xr2.z); dd_ += at2.w * lrl(p2.w + xr2.w);    \
        dd_ += at3.x * lrl(p3.x + xr3.x); dd_ += at3.y * lrl(p3.y + xr3.y);    \
        dd_ += at3.z * lrl(p3.z + xr3.z); dd_ += at3.w * lrl(p3.w + xr3.w);    \
        dst = dd_;                                                             \
    }

    // prologue: shift = logit of first edge
    float m;
    {
        int src0 = g_esrc[jb];
        const float4* lp = (const float4*)(g_xl + (size_t)src0 * DD + h * 16);
        float4 x0 = lp[0], x1 = lp[1], x2 = lp[2], x3 = lp[3];
        DOT16(m, x0, x1, x2, x3);
    }

    float s = 0.f;
    float4 a0 = make_float4(0.f, 0.f, 0.f, 0.f), a1 = a0, a2 = a0, a3 = a0;

    int nIter = (je - jb + 7) >> 3;
    for (int it = 0; it < nIter; it++) {
        int j0 = jb + it * 8 + slot;
        int j1 = j0 + 4;
        bool act0 = (j0 < je), act1 = (j1 < je);
        int s0 = g_esrc[act0 ? j0 : je - 1];
        int s1 = g_esrc[act1 ? j1 : je - 1];
        const float4* lp0 = (const float4*)(g_xl + (size_t)s0 * DD + h * 16);
        const float4* lp1 = (const float4*)(g_xl + (size_t)s1 * DD + h * 16);
        float4 x0 = lp0[0], x1 = lp0[1], x2 = lp0[2], x3 = lp0[3];
        float4 y0 = lp1[0], y1 = lp1[1], y2 = lp1[2], y3 = lp1[3];

        float d0, d1;
        DOT16(d0, x0, x1, x2, x3);
        DOT16(d1, y0, y1, y2, y3);
        float p0 = act0 ? __expf(d0 - m) : 0.f;
        float p1 = act1 ? __expf(d1 - m) : 0.f;
        s += p0 + p1;
        a0.x += p0 * x0.x + p1 * y0.x; a0.y += p0 * x0.y + p1 * y0.y;
        a0.z += p0 * x0.z + p1 * y0.z; a0.w += p0 * x0.w + p1 * y0.w;
        a1.x += p0 * x1.x + p1 * y1.x; a1.y += p0 * x1.y + p1 * y1.y;
        a1.z += p0 * x1.z + p1 * y1.z; a1.w += p0 * x1.w + p1 * y1.w;
        a2.x += p0 * x2.x + p1 * y2.x; a2.y += p0 * x2.y + p1 * y2.y;
        a2.z += p0 * x2.z + p1 * y2.z; a2.w += p0 * x2.w + p1 * y2.w;
        a3.x += p0 * x3.x + p1 * y3.x; a3.y += p0 * x3.y + p1 * y3.y;
        a3.z += p0 * x3.z + p1 * y3.z; a3.w += p0 * x3.w + p1 * y3.w;
    }
#undef DOT16

    // merge 4 slots: plain sums
#pragma unroll
    for (int off = 8; off <= 16; off <<= 1) {
        s += __shfl_xor_sync(0xffffffffu, s, off);
#define MRG(c) c += __shfl_xor_sync(0xffffffffu, c, off)
        MRG(a0.x); MRG(a0.y); MRG(a0.z); MRG(a0.w);
        MRG(a1.x); MRG(a1.y); MRG(a1.z); MRG(a1.w);
        MRG(a2.x); MRG(a2.y); MRG(a2.z); MRG(a2.w);
        MRG(a3.x); MRG(a3.y); MRG(a3.z); MRG(a3.w);
#undef MRG
    }

    if (slot == 0) {
        float inv = 1.f / s;
        const float4* bp = (const float4*)(biasb + h * 16);
        float4 b0 = bp[0], b1 = bp[1], b2 = bp[2], b3 = bp[3];
        float4 o0, o1, o2, o3;
#define FIN(o, a, b) \
        o.x = a.x * inv + b.x; o.x = o.x > 0.f ? o.x : (__expf(o.x) - 1.f); \
        o.y = a.y * inv + b.y; o.y = o.y > 0.f ? o.y : (__expf(o.y) - 1.f); \
        o.z = a.z * inv + b.z; o.z = o.z > 0.f ? o.z : (__expf(o.z) - 1.f); \
        o.w = a.w * inv + b.w; o.w = o.w > 0.f ? o.w : (__expf(o.w) - 1.f)
        FIN(o0, a0, b0); FIN(o1, a1, b1); FIN(o2, a2, b2); FIN(o3, a3, b3);
#undef FIN
        if (round_out) {
            o0.x = f2tf32f(o0.x); o0.y = f2tf32f(o0.y); o0.z = f2tf32f(o0.z); o0.w = f2tf32f(o0.w);
            o1.x = f2tf32f(o1.x); o1.y = f2tf32f(o1.y); o1.z = f2tf32f(o1.z); o1.w = f2tf32f(o1.w);
            o2.x = f2tf32f(o2.x); o2.y = f2tf32f(o2.y); o2.z = f2tf32f(o2.z); o2.w = f2tf32f(o2.w);
            o3.x = f2tf32f(o3.x); o3.y = f2tf32f(o3.y); o3.z = f2tf32f(o3.z); o3.w = f2tf32f(o3.w);
        }
        float4* op = (float4*)(hout + (size_t)gw * DD + h * 16);
        op[0] = o0; op[1] = o1; op[2] = o2; op[3] = o3;
    }
}

// ---------------- global mean pool: run-length accumulate (batch is sorted) ----------------
__global__ __launch_bounds__(128) void pool_kernel(const int* __restrict__ batch) {
    int ch = threadIdx.x;
    int n0 = blockIdx.x * 128;
    int nEnd = n0 + 128; if (nEnd > NN) nEnd = NN;
    if (n0 >= NN) return;

    int cur = batch[n0];
    float acc = 0.f;
    int runlen = 0;
    for (int nd = n0; nd < nEnd; nd++) {
        int gidx = batch[nd];
        if (gidx != cur) {
            atomicAdd(&g_pool[cur * DD + ch], acc);
            if (ch == 0) atomicAdd(&g_pcnt[cur], (float)runlen);
            acc = 0.f; runlen = 0; cur = gidx;
        }
        acc += g_bufA[(size_t)nd * DD + ch];
        runlen++;
    }
    atomicAdd(&g_pool[cur * DD + ch], acc);
    if (ch == 0) atomicAdd(&g_pcnt[cur], (float)runlen);
}

// ---------------- classifier + log_softmax ----------------
__global__ void cls_kernel(const float* __restrict__ Wout,
                           const float* __restrict__ bout,
                           float* __restrict__ out) {
    __shared__ float slog[NG][NC];
    __shared__ float srow[NG];
    int t = threadIdx.x;
    if (t < NG * NC) {
        int g = t / NC, c = t % NC;
        float inv = 1.f / fmaxf(g_pcnt[g], 1.f);
        float acc = 0.f;
        for (int k = 0; k < DD; k++) acc += g_pool[g * DD + k] * Wout[k * NC + c];
        slog[g][c] = acc * inv + bout[c];
    }
    __syncthreads();
    if (t < NG) {
        float mx = -3.0e38f;
        for (int c = 0; c < NC; c++) mx = fmaxf(mx, slog[t][c]);
        float ssum = 0.f;
        for (int c = 0; c < NC; c++) ssum += expf(slog[t][c] - mx);
        srow[t] = mx + logf(ssum);
    }
    __syncthreads();
    if (t < NG * NC) out[t] = slog[t / NC][t % NC] - srow[t / NC];
}

// ---------------- driver ----------------
extern "C" void kernel_launch(void* const* d_in, const int* in_sizes, int n_in,
                              void* d_out, int out_size) {
    const float* x     = (const float*)d_in[0];
    const int*   ei    = (const int*)  d_in[1];
    const int*   batch = (const int*)  d_in[2];
    const float* Wl    = (const float*)d_in[3];
    const float* bl    = (const float*)d_in[4];
    const float* Wr    = (const float*)d_in[5];
    const float* br    = (const float*)d_in[6];
    const float* att   = (const float*)d_in[7];
    const float* bias  = (const float*)d_in[8];
    const float* Wout  = (const float*)d_in[9];
    const float* bout  = (const float*)d_in[10];
    float* out = (float*)d_out;

    dim3 ggrid((NN + GBM - 1) / GBM, 4);

    // launch order chosen so that 0-based launch #3 (the one ncu captures)
    // is the layer-0 GEMM: init(0), pack(1), roundx(2), gemm0(3), ...
    init_kernel<<<(NN + 255) / 256, 256>>>();
    pack_kernel<<<(NL * DD * 256 + NL * 256 + 255) / 256, 256>>>(Wl, bl, Wr, br);
    roundx_kernel<<<(NN * DD / 4 + 255) / 256, 256>>>(x);
    gemm_tc_kernel<<<ggrid, 256>>>(0);          // layer-0 GEMM (hoisted; not relaunched below)

    count_kernel<<<(NE + 255) / 256, 256>>>(ei);
    scan1_kernel<<<SCAN_BLOCKS, 1024>>>();
    scan2_kernel<<<1, 32>>>();
    scan3_kernel<<<SCAN_BLOCKS, 1024>>>();
    scatter_kernel<<<(NE + 255) / 256, 256>>>(ei);

    for (int l = 0; l < NL; l++) {
        if (l > 0) gemm_tc_kernel<<<ggrid, 256>>>(l);
        int outbuf = (l % 2 == 0) ? 0 : 1;
        int round_out = (l < NL - 1) ? 1 : 0;
        gat_kernel<<<(NN * 32 + 255) / 256, 256>>>(att + l * DD, bias + l * DD, outbuf, round_out);
    }

    pool_kernel<<<(NN + 127) / 128, 128>>>(batch);
    cls_kernel<<<1, 640>>>(Wout, bout, out);
}

// round 9
// speedup vs baseline: 1.2145x; 1.2145x over previous
#include <cuda_runtime.h>
#include <cstdint>

#define NN 50000
#define NE_IN 800000
#define NE (NE_IN + NN)
#define DD 128
#define NG 64
#define NC 10
#define NL 5

#define SCAN_BLOCKS ((NN + 1023) / 1024)

// ---------------- static device scratch ----------------
__device__ __align__(16) float g_bufA[NN * DD];
__device__ __align__(16) float g_bufB[NN * DD];
__device__ __align__(16) float g_xl[NN * DD];
__device__ __align__(16) float g_xr[NN * DD];
__device__ __align__(16) float g_Wpack[NL * DD * 256];
__device__ __align__(16) float g_bpack[NL * 256];
__device__ int   g_rowptr[NN + 1];
__device__ int   g_cursor[NN];
__device__ int   g_esrc[NE];
__device__ int   g_cnt[NN];
__device__ int   g_bsum[64];
__device__ __align__(16) float g_pool[NG * DD];
__device__ float g_pcnt[NG];

__device__ __forceinline__ uint32_t f2tf32(float f) {
    uint32_t u;
    asm volatile("cvt.rna.tf32.f32 %0, %1;" : "=r"(u) : "f"(f));
    return u;
}
__device__ __forceinline__ float f2tf32f(float f) {
    uint32_t u = f2tf32(f);
    return __uint_as_float(u);
}

// ---------------- init ----------------
__global__ void init_kernel() {
    int i = blockIdx.x * blockDim.x + threadIdx.x;
    if (i < NN) g_cnt[i] = 0;
    if (i < NG * DD) g_pool[i] = 0.f;
    if (i < NG) g_pcnt[i] = 0.f;
}

// ---------------- round x (layer-0 input) into g_bufB as tf32 ----------------
__global__ void roundx_kernel(const float* __restrict__ x) {
    int i = blockIdx.x * blockDim.x + threadIdx.x;
    if (i < NN * DD / 4) {
        float4 v = ((const float4*)x)[i];
        v.x = f2tf32f(v.x); v.y = f2tf32f(v.y);
        v.z = f2tf32f(v.z); v.w = f2tf32f(v.w);
        ((float4*)g_bufB)[i] = v;
    }
}

// ---------------- CSR build ----------------
__global__ void count_kernel(const int* __restrict__ ei) {
    int e = blockIdx.x * blockDim.x + threadIdx.x;
    if (e >= NE) return;
    int d = (e < NE_IN) ? ei[NE_IN + e] : (e - NE_IN);
    atomicAdd(&g_cnt[d], 1);
}

__global__ void scan1_kernel() {
    __shared__ int wsum[32];
    int tid = threadIdx.x;
    int i = blockIdx.x * 1024 + tid;
    int v = (i < NN) ? g_cnt[i] : 0;
    int x = v;
#pragma unroll
    for (int off = 1; off < 32; off <<= 1) {
        int y = __shfl_up_sync(0xffffffffu, x, off);
        if ((tid & 31) >= off) x += y;
    }
    if ((tid & 31) == 31) wsum[tid >> 5] = x;
    __syncthreads();
    if (tid < 32) {
        int w = wsum[tid];
        int xs = w;
#pragma unroll
        for (int off = 1; off < 32; off <<= 1) {
            int y = __shfl_up_sync(0xffffffffu, xs, off);
            if (tid >= off) xs += y;
        }
        wsum[tid] = xs - w;
    }
    __syncthreads();
    int incl = x + wsum[tid >> 5];
    if (i < NN) g_rowptr[i] = incl - v;
    if (tid == 1023) g_bsum[blockIdx.x] = incl;
}

__global__ void scan2_kernel() {
    if (threadIdx.x == 0) {
        int acc = 0;
        for (int b = 0; b < SCAN_BLOCKS; b++) { int t = g_bsum[b]; g_bsum[b] = acc; acc += t; }
    }
}

__global__ void scan3_kernel() {
    int i = blockIdx.x * 1024 + threadIdx.x;
    if (i < NN) {
        int r = g_rowptr[i] + g_bsum[blockIdx.x];
        g_rowptr[i] = r;
        g_cursor[i] = r;
    }
    if (i == 0) g_rowptr[NN] = NE;
}

__global__ void scatter_kernel(const int* __restrict__ ei) {
    int e = blockIdx.x * blockDim.x + threadIdx.x;
    if (e >= NE) return;
    int s, d;
    if (e < NE_IN) { s = ei[e]; d = ei[NE_IN + e]; }
    else           { s = e - NE_IN; d = s; }
    int pos = atomicAdd(&g_cursor[d], 1);
    g_esrc[pos] = s;
}

// ---------------- pack weights (tf32-rounded) ----------------
__global__ void pack_kernel(const float* __restrict__ Wl, const float* __restrict__ bl,
                            const float* __restrict__ Wr, const float* __restrict__ br) {
    int i = blockIdx.x * blockDim.x + threadIdx.x;
    int WTOT = NL * DD * 256;
    if (i < WTOT) {
        int l = i / (DD * 256);
        int rem = i - l * DD * 256;
        int k = rem >> 8, j = rem & 255;
        float w = (j < DD) ? Wl[(l * DD + k) * DD + j]
                           : Wr[(l * DD + k) * DD + (j - DD)];
        g_Wpack[i] = f2tf32f(w);
    } else if (i < WTOT + NL * 256) {
        int r = i - WTOT;
        int l = r >> 8, j = r & 255;
        g_bpack[r] = (j < DD) ? bl[l * DD + j] : br[l * DD + j - DD];
    }
}

// ---------------- tf32 tensor-core GEMM (2-stage, proven in R5) ----------------
#define GBM 128
#define GBN 64
#define GBK 16

__device__ __forceinline__ void cpa16(void* smem, const void* g) {
    unsigned sa = (unsigned)__cvta_generic_to_shared(smem);
    asm volatile("cp.async.cg.shared.global [%0], [%1], 16;" :: "r"(sa), "l"(g));
}
__device__ __forceinline__ void mma8(float* c, const uint32_t* a, const uint32_t* b) {
    asm volatile(
        "mma.sync.aligned.m16n8k8.row.col.f32.tf32.tf32.f32 "
        "{%0,%1,%2,%3},{%4,%5,%6,%7},{%8,%9},{%0,%1,%2,%3};"
        : "+f"(c[0]), "+f"(c[1]), "+f"(c[2]), "+f"(c[3])
        : "r"(a[0]), "r"(a[1]), "r"(a[2]), "r"(a[3]), "r"(b[0]), "r"(b[1]));
}

__global__ __launch_bounds__(256) void gemm_tc_kernel(int l) {
    const float* A = (l & 1) ? g_bufA : g_bufB;   // l=0 reads pre-rounded x in bufB
    __shared__ float As[2][GBM][GBK + 4];
    __shared__ float Bs[2][GBK][GBN + 4];

    int tid  = threadIdx.x;
    int lane = tid & 31;
    int warp = tid >> 5;
    int wm = warp >> 1, wn = warp & 1;
    int g = lane >> 2, t = lane & 3;
    int bm0 = blockIdx.x * GBM;

    const float* Wb = g_Wpack + l * (DD * 256) + blockIdx.y * GBN;

    float acc[2][4][4];
#pragma unroll
    for (int mt = 0; mt < 2; mt++)
#pragma unroll
        for (int nt = 0; nt < 4; nt++)
#pragma unroll
            for (int c = 0; c < 4; c++) acc[mt][nt][c] = 0.f;

    auto load_stage = [&](int buf, int k0) {
#pragma unroll
        for (int i = 0; i < 2; i++) {
            int idx = tid + i * 256;
            int row = idx >> 2, q = idx & 3;
            int gr = bm0 + row; if (gr >= NN) gr = NN - 1;
            cpa16(&As[buf][row][q * 4], A + (size_t)gr * DD + k0 + q * 4);
        }
        {
            int row = tid >> 4, q = tid & 15;
            cpa16(&Bs[buf][row][q * 4], Wb + (k0 + row) * 256 + q * 4);
        }
        asm volatile("cp.async.commit_group;");
    };

    load_stage(0, 0);

    int buf = 0;
#pragma unroll
    for (int kt = 0; kt < DD / GBK; kt++) {
        if (kt + 1 < DD / GBK) {
            load_stage(buf ^ 1, (kt + 1) * GBK);
            asm volatile("cp.async.wait_group 1;");
        } else {
            asm volatile("cp.async.wait_group 0;");
        }
        __syncthreads();

#pragma unroll
        for (int ks = 0; ks < 2; ks++) {
            int kk = ks * 8;
            uint32_t af[2][4];
#pragma unroll
            for (int mt = 0; mt < 2; mt++) {
                int r0 = wm * 32 + mt * 16 + g;
                af[mt][0] = *(const uint32_t*)&As[buf][r0][kk + t];
                af[mt][1] = *(const uint32_t*)&As[buf][r0 + 8][kk + t];
                af[mt][2] = *(const uint32_t*)&As[buf][r0][kk + t + 4];
                af[mt][3] = *(const uint32_t*)&As[buf][r0 + 8][kk + t + 4];
            }
            uint32_t bf[4][2];
#pragma unroll
            for (int nt = 0; nt < 4; nt++) {
                int c0 = wn * 32 + nt * 8 + g;
                bf[nt][0] = *(const uint32_t*)&Bs[buf][kk + t][c0];
                bf[nt][1] = *(const uint32_t*)&Bs[buf][kk + t + 4][c0];
            }
#pragma unroll
            for (int mt = 0; mt < 2; mt++)
#pragma unroll
                for (int nt = 0; nt < 4; nt++)
                    mma8(acc[mt][nt], af[mt], bf[nt]);
        }
        __syncthreads();
        buf ^= 1;
    }

    int cbase = blockIdx.y * GBN + wn * 32;
    const float* bp = g_bpack + l * 256;
    float* obase = (blockIdx.y < 2) ? g_xl : g_xr;
    int coff = (blockIdx.y < 2) ? cbase : cbase - DD;
#pragma unroll
    for (int mt = 0; mt < 2; mt++) {
        int r0 = bm0 + wm * 32 + mt * 16 + g;
#pragma unroll
        for (int nt = 0; nt < 4; nt++) {
            int cb = cbase + nt * 8 + 2 * t;
            int c  = coff + nt * 8 + 2 * t;
            float bx = bp[cb], by = bp[cb + 1];
            if (r0 < NN) {
                float2 v = make_float2(acc[mt][nt][0] + bx, acc[mt][nt][1] + by);
                *(float2*)(obase + (size_t)r0 * DD + c) = v;
            }
            if (r0 + 8 < NN) {
                float2 v = make_float2(acc[mt][nt][2] + bx, acc[mt][nt][3] + by);
                *(float2*)(obase + (size_t)(r0 + 8) * DD + c) = v;
            }
        }
    }
}

// ---------------- GAT edge aggregation ----------------
// one warp per dst node; lane = slot(lane>>3)*8 + head(lane&7)
// 4 edges/iter; next src index prefetched before this iter's gathers
// softmax shift = 0 (exact: shift cancels; logits O(1), no overflow)
__device__ __forceinline__ float lrl(float z) { return z > 0.f ? z : 0.2f * z; }

__global__ __launch_bounds__(256) void gat_kernel(const float* __restrict__ attb,
                                                  const float* __restrict__ biasb,
                                                  int outbuf, int round_out) {
    int gw = (blockIdx.x * blockDim.x + threadIdx.x) >> 5;
    int lane = threadIdx.x & 31;
    if (gw >= NN) return;
    float* hout = (outbuf == 0) ? g_bufA : g_bufB;

    int slot = lane >> 3, h = lane & 7;
    const float4* ap = (const float4*)(attb + h * 16);
    float4 at0 = ap[0], at1 = ap[1], at2 = ap[2], at3 = ap[3];
    const float4* xp = (const float4*)(g_xr + (size_t)gw * DD + h * 16);
    float4 xr0 = xp[0], xr1 = xp[1], xr2 = xp[2], xr3 = xp[3];

    int jb = g_rowptr[gw], je = g_rowptr[gw + 1];

    float s = 0.f;
    float4 a0 = make_float4(0.f, 0.f, 0.f, 0.f), a1 = a0, a2 = a0, a3 = a0;

    int j = jb + slot;
    int src_next = __ldg(&g_esrc[j < je ? j : je - 1]);
    int nIter = (je - jb + 3) >> 2;

    for (int it = 0; it < nIter; it++) {
        int src = src_next;
        bool act = (j < je);
        int jn = j + 4;
        // prefetch next iteration's index before issuing this iteration's gathers
        src_next = __ldg(&g_esrc[jn < je ? jn : je - 1]);

        const float4* lp = (const float4*)(g_xl + (size_t)src * DD + h * 16);
        float4 x0 = __ldg(lp + 0), x1 = __ldg(lp + 1);
        float4 x2 = __ldg(lp + 2), x3 = __ldg(lp + 3);

        float d = 0.f;
        d += at0.x * lrl(x0.x + xr0.x); d += at0.y * lrl(x0.y + xr0.y);
        d += at0.z * lrl(x0.z + xr0.z); d += at0.w * lrl(x0.w + xr0.w);
        d += at1.x * lrl(x1.x + xr1.x); d += at1.y * lrl(x1.y + xr1.y);
        d += at1.z * lrl(x1.z + xr1.z); d += at1.w * lrl(x1.w + xr1.w);
        d += at2.x * lrl(x2.x + xr2.x); d += at2.y * lrl(x2.y + xr2.y);
        d += at2.z * lrl(x2.z + xr2.z); d += at2.w * lrl(x2.w + xr2.w);
        d += at3.x * lrl(x3.x + xr3.x); d += at3.y * lrl(x3.y + xr3.y);
        d += at3.z * lrl(x3.z + xr3.z); d += at3.w * lrl(x3.w + xr3.w);

        float p = act ? __expf(d) : 0.f;
        s += p;
        a0.x += p * x0.x; a0.y += p * x0.y; a0.z += p * x0.z; a0.w += p * x0.w;
        a1.x += p * x1.x; a1.y += p * x1.y; a1.z += p * x1.z; a1.w += p * x1.w;
        a2.x += p * x2.x; a2.y += p * x2.y; a2.z += p * x2.z; a2.w += p * x2.w;
        a3.x += p * x3.x; a3.y += p * x3.y; a3.z += p * x3.z; a3.w += p * x3.w;
        j = jn;
    }

    // merge 4 slots
#pragma unroll
    for (int off = 8; off <= 16; off <<= 1) {
        s += __shfl_xor_sync(0xffffffffu, s, off);
#define MRG(c) c += __shfl_xor_sync(0xffffffffu, c, off)
        MRG(a0.x); MRG(a0.y); MRG(a0.z); MRG(a0.w);
        MRG(a1.x); MRG(a1.y); MRG(a1.z); MRG(a1.w);
        MRG(a2.x); MRG(a2.y); MRG(a2.z); MRG(a2.w);
        MRG(a3.x); MRG(a3.y); MRG(a3.z); MRG(a3.w);
#undef MRG
    }

    if (slot == 0) {
        float inv = 1.f / s;
        const float4* bp = (const float4*)(biasb + h * 16);
        float4 b0 = bp[0], b1 = bp[1], b2 = bp[2], b3 = bp[3];
        float4 o0, o1, o2, o3;
#define FIN(o, a, b) \
        o.x = a.x * inv + b.x; o.x = o.x > 0.f ? o.x : (__expf(o.x) - 1.f); \
        o.y = a.y * inv + b.y; o.y = o.y > 0.f ? o.y : (__expf(o.y) - 1.f); \
        o.z = a.z * inv + b.z; o.z = o.z > 0.f ? o.z : (__expf(o.z) - 1.f); \
        o.w = a.w * inv + b.w; o.w = o.w > 0.f ? o.w : (__expf(o.w) - 1.f)
        FIN(o0, a0, b0); FIN(o1, a1, b1); FIN(o2, a2, b2); FIN(o3, a3, b3);
#undef FIN
        if (round_out) {
            o0.x = f2tf32f(o0.x); o0.y = f2tf32f(o0.y); o0.z = f2tf32f(o0.z); o0.w = f2tf32f(o0.w);
            o1.x = f2tf32f(o1.x); o1.y = f2tf32f(o1.y); o1.z = f2tf32f(o1.z); o1.w = f2tf32f(o1.w);
            o2.x = f2tf32f(o2.x); o2.y = f2tf32f(o2.y); o2.z = f2tf32f(o2.z); o2.w = f2tf32f(o2.w);
            o3.x = f2tf32f(o3.x); o3.y = f2tf32f(o3.y); o3.z = f2tf32f(o3.z); o3.w = f2tf32f(o3.w);
        }
        float4* op = (float4*)(hout + (size_t)gw * DD + h * 16);
        op[0] = o0; op[1] = o1; op[2] = o2; op[3] = o3;
    }
}

// ---------------- global mean pool ----------------
__global__ __launch_bounds__(128) void pool_kernel(const int* __restrict__ batch) {
    int ch = threadIdx.x;
    int n0 = blockIdx.x * 128;
    int nEnd = n0 + 128; if (nEnd > NN) nEnd = NN;
    if (n0 >= NN) return;

    int cur = batch[n0];
    float acc = 0.f;
    int runlen = 0;
    for (int nd = n0; nd < nEnd; nd++) {
        int gidx = batch[nd];
        if (gidx != cur) {
            atomicAdd(&g_pool[cur * DD + ch], acc);
            if (ch == 0) atomicAdd(&g_pcnt[cur], (float)runlen);
            acc = 0.f; runlen = 0; cur = gidx;
        }
        acc += g_bufA[(size_t)nd * DD + ch];
        runlen++;
    }
    atomicAdd(&g_pool[cur * DD + ch], acc);
    if (ch == 0) atomicAdd(&g_pcnt[cur], (float)runlen);
}

// ---------------- classifier + log_softmax ----------------
__global__ void cls_kernel(const float* __restrict__ Wout,
                           const float* __restrict__ bout,
                           float* __restrict__ out) {
    __shared__ float slog[NG][NC];
    __shared__ float srow[NG];
    int t = threadIdx.x;
    if (t < NG * NC) {
        int g = t / NC, c = t % NC;
        float inv = 1.f / fmaxf(g_pcnt[g], 1.f);
        float acc = 0.f;
        for (int k = 0; k < DD; k++) acc += g_pool[g * DD + k] * Wout[k * NC + c];
        slog[g][c] = acc * inv + bout[c];
    }
    __syncthreads();
    if (t < NG) {
        float mx = -3.0e38f;
        for (int c = 0; c < NC; c++) mx = fmaxf(mx, slog[t][c]);
        float ssum = 0.f;
        for (int c = 0; c < NC; c++) ssum += expf(slog[t][c] - mx);
        srow[t] = mx + logf(ssum);
    }
    __syncthreads();
    if (t < NG * NC) out[t] = slog[t / NC][t % NC] - srow[t / NC];
}

// ---------------- driver ----------------
extern "C" void kernel_launch(void* const* d_in, const int* in_sizes, int n_in,
                              void* d_out, int out_size) {
    const float* x     = (const float*)d_in[0];
    const int*   ei    = (const int*)  d_in[1];
    const int*   batch = (const int*)  d_in[2];
    const float* Wl    = (const float*)d_in[3];
    const float* bl    = (const float*)d_in[4];
    const float* Wr    = (const float*)d_in[5];
    const float* br    = (const float*)d_in[6];
    const float* att   = (const float*)d_in[7];
    const float* bias  = (const float*)d_in[8];
    const float* Wout  = (const float*)d_in[9];
    const float* bout  = (const float*)d_in[10];
    float* out = (float*)d_out;

    dim3 ggrid((NN + GBM - 1) / GBM, 4);

    // launch #3 (0-based) = layer-0 GEMM for ncu capture
    init_kernel<<<(NN + 255) / 256, 256>>>();
    pack_kernel<<<(NL * DD * 256 + NL * 256 + 255) / 256, 256>>>(Wl, bl, Wr, br);
    roundx_kernel<<<(NN * DD / 4 + 255) / 256, 256>>>(x);
    gemm_tc_kernel<<<ggrid, 256>>>(0);

    count_kernel<<<(NE + 255) / 256, 256>>>(ei);
    scan1_kernel<<<SCAN_BLOCKS, 1024>>>();
    scan2_kernel<<<1, 32>>>();
    scan3_kernel<<<SCAN_BLOCKS, 1024>>>();
    scatter_kernel<<<(NE + 255) / 256, 256>>>(ei);

    for (int l = 0; l < NL; l++) {
        if (l > 0) gemm_tc_kernel<<<ggrid, 256>>>(l);
        int outbuf = (l % 2 == 0) ? 0 : 1;
        int round_out = (l < NL - 1) ? 1 : 0;
        gat_kernel<<<(NN * 32 + 255) / 256, 256>>>(att + l * DD, bias + l * DD, outbuf, round_out);
    }

    pool_kernel<<<(NN + 127) / 128, 128>>>(batch);
    cls_kernel<<<1, 640>>>(Wout, bout, out);
}

// round 10
// speedup vs baseline: 1.4371x; 1.1833x over previous
#include <cuda_runtime.h>
#include <cuda_fp16.h>
#include <cstdint>

#define NN 50000
#define NE_IN 800000
#define NE (NE_IN + NN)
#define DD 128
#define NG 64
#define NC 10
#define NL 5

#define SCAN_BLOCKS ((NN + 1023) / 1024)

// ---------------- static device scratch ----------------
__device__ __align__(16) float g_bufA[NN * DD];
__device__ __align__(16) float g_bufB[NN * DD];
__device__ __align__(16) __half g_xlh[NN * DD];    // fp16 xl (message/logit source)
__device__ __align__(16) float g_xr[NN * DD];
__device__ __align__(16) float g_Wpack[NL * DD * 256];
__device__ __align__(16) float g_bpack[NL * 256];
__device__ int   g_rowptr[NN + 1];
__device__ int   g_cursor[NN];
__device__ int   g_esrc[NE];
__device__ int   g_cnt[NN];
__device__ int   g_bsum[64];
__device__ __align__(16) float g_pool[NG * DD];
__device__ float g_pcnt[NG];

__device__ __forceinline__ uint32_t f2tf32(float f) {
    uint32_t u;
    asm volatile("cvt.rna.tf32.f32 %0, %1;" : "=r"(u) : "f"(f));
    return u;
}
__device__ __forceinline__ float f2tf32f(float f) {
    uint32_t u = f2tf32(f);
    return __uint_as_float(u);
}

// ---------------- init ----------------
__global__ void init_kernel() {
    int i = blockIdx.x * blockDim.x + threadIdx.x;
    if (i < NN) g_cnt[i] = 0;
    if (i < NG * DD) g_pool[i] = 0.f;
    if (i < NG) g_pcnt[i] = 0.f;
}

// ---------------- round x (layer-0 input) into g_bufB as tf32 ----------------
__global__ void roundx_kernel(const float* __restrict__ x) {
    int i = blockIdx.x * blockDim.x + threadIdx.x;
    if (i < NN * DD / 4) {
        float4 v = ((const float4*)x)[i];
        v.x = f2tf32f(v.x); v.y = f2tf32f(v.y);
        v.z = f2tf32f(v.z); v.w = f2tf32f(v.w);
        ((float4*)g_bufB)[i] = v;
    }
}

// ---------------- CSR build ----------------
__global__ void count_kernel(const int* __restrict__ ei) {
    int e = blockIdx.x * blockDim.x + threadIdx.x;
    if (e >= NE) return;
    int d = (e < NE_IN) ? ei[NE_IN + e] : (e - NE_IN);
    atomicAdd(&g_cnt[d], 1);
}

__global__ void scan1_kernel() {
    __shared__ int wsum[32];
    int tid = threadIdx.x;
    int i = blockIdx.x * 1024 + tid;
    int v = (i < NN) ? g_cnt[i] : 0;
    int x = v;
#pragma unroll
    for (int off = 1; off < 32; off <<= 1) {
        int y = __shfl_up_sync(0xffffffffu, x, off);
        if ((tid & 31) >= off) x += y;
    }
    if ((tid & 31) == 31) wsum[tid >> 5] = x;
    __syncthreads();
    if (tid < 32) {
        int w = wsum[tid];
        int xs = w;
#pragma unroll
        for (int off = 1; off < 32; off <<= 1) {
            int y = __shfl_up_sync(0xffffffffu, xs, off);
            if (tid >= off) xs += y;
        }
        wsum[tid] = xs - w;
    }
    __syncthreads();
    int incl = x + wsum[tid >> 5];
    if (i < NN) g_rowptr[i] = incl - v;
    if (tid == 1023) g_bsum[blockIdx.x] = incl;
}

__global__ void scan2_kernel() {
    if (threadIdx.x == 0) {
        int acc = 0;
        for (int b = 0; b < SCAN_BLOCKS; b++) { int t = g_bsum[b]; g_bsum[b] = acc; acc += t; }
    }
}

__global__ void scan3_kernel() {
    int i = blockIdx.x * 1024 + threadIdx.x;
    if (i < NN) {
        int r = g_rowptr[i] + g_bsum[blockIdx.x];
        g_rowptr[i] = r;
        g_cursor[i] = r;
    }
    if (i == 0) g_rowptr[NN] = NE;
}

__global__ void scatter_kernel(const int* __restrict__ ei) {
    int e = blockIdx.x * blockDim.x + threadIdx.x;
    if (e >= NE) return;
    int s, d;
    if (e < NE_IN) { s = ei[e]; d = ei[NE_IN + e]; }
    else           { s = e - NE_IN; d = s; }
    int pos = atomicAdd(&g_cursor[d], 1);
    g_esrc[pos] = s;
}

// ---------------- pack weights (tf32-rounded) ----------------
__global__ void pack_kernel(const float* __restrict__ Wl, const float* __restrict__ bl,
                            const float* __restrict__ Wr, const float* __restrict__ br) {
    int i = blockIdx.x * blockDim.x + threadIdx.x;
    int WTOT = NL * DD * 256;
    if (i < WTOT) {
        int l = i / (DD * 256);
        int rem = i - l * DD * 256;
        int k = rem >> 8, j = rem & 255;
        float w = (j < DD) ? Wl[(l * DD + k) * DD + j]
                           : Wr[(l * DD + k) * DD + (j - DD)];
        g_Wpack[i] = f2tf32f(w);
    } else if (i < WTOT + NL * 256) {
        int r = i - WTOT;
        int l = r >> 8, j = r & 255;
        g_bpack[r] = (j < DD) ? bl[l * DD + j] : br[l * DD + j - DD];
    }
}

// ---------------- tf32 tensor-core GEMM, BK=32, 2-stage ----------------
#define GBM 128
#define GBN 64
#define GBK 32
#define NKT (DD / GBK)   // 4

__device__ __forceinline__ void cpa16(void* smem, const void* g) {
    unsigned sa = (unsigned)__cvta_generic_to_shared(smem);
    asm volatile("cp.async.cg.shared.global [%0], [%1], 16;" :: "r"(sa), "l"(g));
}
__device__ __forceinline__ void mma8(float* c, const uint32_t* a, const uint32_t* b) {
    asm volatile(
        "mma.sync.aligned.m16n8k8.row.col.f32.tf32.tf32.f32 "
        "{%0,%1,%2,%3},{%4,%5,%6,%7},{%8,%9},{%0,%1,%2,%3};"
        : "+f"(c[0]), "+f"(c[1]), "+f"(c[2]), "+f"(c[3])
        : "r"(a[0]), "r"(a[1]), "r"(a[2]), "r"(a[3]), "r"(b[0]), "r"(b[1]));
}

__global__ __launch_bounds__(256) void gemm_tc_kernel(int l) {
    const float* A = (l & 1) ? g_bufA : g_bufB;   // l=0 reads pre-rounded x in bufB
    __shared__ float As[2][GBM][GBK + 4];   // 128 x 36
    __shared__ float Bs[2][GBK][GBN + 4];   // 32 x 68

    int tid  = threadIdx.x;
    int lane = tid & 31;
    int warp = tid >> 5;
    int wm = warp >> 1, wn = warp & 1;
    int g = lane >> 2, t = lane & 3;
    int bm0 = blockIdx.x * GBM;

    const float* Wb = g_Wpack + l * (DD * 256) + blockIdx.y * GBN;

    float acc[2][4][4];
#pragma unroll
    for (int mt = 0; mt < 2; mt++)
#pragma unroll
        for (int nt = 0; nt < 4; nt++)
#pragma unroll
            for (int c = 0; c < 4; c++) acc[mt][nt][c] = 0.f;

    auto load_stage = [&](int buf, int k0) {
        // A: 128 rows x 32 cols = 1024 float4 -> 4 per thread
#pragma unroll
        for (int i = 0; i < 4; i++) {
            int idx = tid + i * 256;
            int row = idx >> 3, q = idx & 7;
            int gr = bm0 + row; if (gr >= NN) gr = NN - 1;
            cpa16(&As[buf][row][q * 4], A + (size_t)gr * DD + k0 + q * 4);
        }
        // B: 32 rows x 64 cols = 512 float4 -> 2 per thread
#pragma unroll
        for (int i = 0; i < 2; i++) {
            int idx = tid + i * 256;
            int row = idx >> 4, q = idx & 15;
            cpa16(&Bs[buf][row][q * 4], Wb + (k0 + row) * 256 + q * 4);
        }
        asm volatile("cp.async.commit_group;");
    };

    load_stage(0, 0);

    int buf = 0;
#pragma unroll
    for (int kt = 0; kt < NKT; kt++) {
        if (kt + 1 < NKT) {
            load_stage(buf ^ 1, (kt + 1) * GBK);
            asm volatile("cp.async.wait_group 1;");
        } else {
            asm volatile("cp.async.wait_group 0;");
        }
        __syncthreads();

#pragma unroll
        for (int ks = 0; ks < 4; ks++) {
            int kk = ks * 8;
            uint32_t af[2][4];
#pragma unroll
            for (int mt = 0; mt < 2; mt++) {
                int r0 = wm * 32 + mt * 16 + g;
                af[mt][0] = *(const uint32_t*)&As[buf][r0][kk + t];
                af[mt][1] = *(const uint32_t*)&As[buf][r0 + 8][kk + t];
                af[mt][2] = *(const uint32_t*)&As[buf][r0][kk + t + 4];
                af[mt][3] = *(const uint32_t*)&As[buf][r0 + 8][kk + t + 4];
            }
            uint32_t bf[4][2];
#pragma unroll
            for (int nt = 0; nt < 4; nt++) {
                int c0 = wn * 32 + nt * 8 + g;
                bf[nt][0] = *(const uint32_t*)&Bs[buf][kk + t][c0];
                bf[nt][1] = *(const uint32_t*)&Bs[buf][kk + t + 4][c0];
            }
#pragma unroll
            for (int mt = 0; mt < 2; mt++)
#pragma unroll
                for (int nt = 0; nt < 4; nt++)
                    mma8(acc[mt][nt], af[mt], bf[nt]);
        }
        __syncthreads();
        buf ^= 1;
    }

    // epilogue: cols [0,128) -> g_xlh (fp16), cols [128,256) -> g_xr (fp32)
    int cbase = blockIdx.y * GBN + wn * 32;
    const float* bp = g_bpack + l * 256;
    bool isXL = (blockIdx.y < 2);
    int coff = isXL ? cbase : cbase - DD;
#pragma unroll
    for (int mt = 0; mt < 2; mt++) {
        int r0 = bm0 + wm * 32 + mt * 16 + g;
#pragma unroll
        for (int nt = 0; nt < 4; nt++) {
            int cb = cbase + nt * 8 + 2 * t;
            int c  = coff + nt * 8 + 2 * t;
            float bx = bp[cb], by = bp[cb + 1];
            if (r0 < NN) {
                float vx = acc[mt][nt][0] + bx, vy = acc[mt][nt][1] + by;
                if (isXL) *(__half2*)(g_xlh + (size_t)r0 * DD + c) = __floats2half2_rn(vx, vy);
                else      *(float2*)(g_xr + (size_t)r0 * DD + c) = make_float2(vx, vy);
            }
            if (r0 + 8 < NN) {
                float vx = acc[mt][nt][2] + bx, vy = acc[mt][nt][3] + by;
                if (isXL) *(__half2*)(g_xlh + (size_t)(r0 + 8) * DD + c) = __floats2half2_rn(vx, vy);
                else      *(float2*)(g_xr + (size_t)(r0 + 8) * DD + c) = make_float2(vx, vy);
            }
        }
    }
}

// ---------------- GAT edge aggregation (fp16 xl gathers) ----------------
// one warp per dst node; lane = slot(lane>>3)*8 + head(lane&7)
// 4 edges/iter; next src index prefetched before this iter's gathers
// softmax shift = 0 (exact: shift cancels; logits O(1), no overflow)
__device__ __forceinline__ float lrl(float z) { return z > 0.f ? z : 0.2f * z; }

__global__ __launch_bounds__(256) void gat_kernel(const float* __restrict__ attb,
                                                  const float* __restrict__ biasb,
                                                  int outbuf, int round_out) {
    int gw = (blockIdx.x * blockDim.x + threadIdx.x) >> 5;
    int lane = threadIdx.x & 31;
    if (gw >= NN) return;
    float* hout = (outbuf == 0) ? g_bufA : g_bufB;

    int slot = lane >> 3, h = lane & 7;

    float at[16], xr[16], ac[16];
#pragma unroll
    for (int c = 0; c < 4; c++) {
        float4 a4 = ((const float4*)(attb + h * 16))[c];
        at[4 * c + 0] = a4.x; at[4 * c + 1] = a4.y; at[4 * c + 2] = a4.z; at[4 * c + 3] = a4.w;
        float4 r4 = ((const float4*)(g_xr + (size_t)gw * DD + h * 16))[c];
        xr[4 * c + 0] = r4.x; xr[4 * c + 1] = r4.y; xr[4 * c + 2] = r4.z; xr[4 * c + 3] = r4.w;
    }
#pragma unroll
    for (int c = 0; c < 16; c++) ac[c] = 0.f;

    int jb = g_rowptr[gw], je = g_rowptr[gw + 1];
    float s = 0.f;

    int j = jb + slot;
    int src_next = __ldg(&g_esrc[j < je ? j : je - 1]);
    int nIter = (je - jb + 3) >> 2;

    for (int it = 0; it < nIter; it++) {
        int src = src_next;
        bool act = (j < je);
        int jn = j + 4;
        src_next = __ldg(&g_esrc[jn < je ? jn : je - 1]);

        const uint4* lp = (const uint4*)(g_xlh + (size_t)src * DD + h * 16);
        uint4 u0 = __ldg(lp + 0);
        uint4 u1 = __ldg(lp + 1);

        float xs[16];
        {
            const __half2* hh0 = (const __half2*)&u0;
            const __half2* hh1 = (const __half2*)&u1;
#pragma unroll
            for (int k = 0; k < 4; k++) {
                float2 f = __half22float2(hh0[k]);
                xs[2 * k + 0] = f.x; xs[2 * k + 1] = f.y;
            }
#pragma unroll
            for (int k = 0; k < 4; k++) {
                float2 f = __half22float2(hh1[k]);
                xs[8 + 2 * k + 0] = f.x; xs[8 + 2 * k + 1] = f.y;
            }
        }

        float d = 0.f;
#pragma unroll
        for (int c = 0; c < 16; c++) d += at[c] * lrl(xs[c] + xr[c]);

        float p = act ? __expf(d) : 0.f;
        s += p;
#pragma unroll
        for (int c = 0; c < 16; c++) ac[c] += p * xs[c];
        j = jn;
    }

    // merge 4 slots
#pragma unroll
    for (int off = 8; off <= 16; off <<= 1) {
        s += __shfl_xor_sync(0xffffffffu, s, off);
#pragma unroll
        for (int c = 0; c < 16; c++) ac[c] += __shfl_xor_sync(0xffffffffu, ac[c], off);
    }

    if (slot == 0) {
        float inv = 1.f / s;
        float o[16];
#pragma unroll
        for (int c = 0; c < 4; c++) {
            float4 b4 = ((const float4*)(biasb + h * 16))[c];
            o[4 * c + 0] = ac[4 * c + 0] * inv + b4.x;
            o[4 * c + 1] = ac[4 * c + 1] * inv + b4.y;
            o[4 * c + 2] = ac[4 * c + 2] * inv + b4.z;
            o[4 * c + 3] = ac[4 * c + 3] * inv + b4.w;
        }
#pragma unroll
        for (int c = 0; c < 16; c++) {
            float v = o[c];
            v = v > 0.f ? v : (__expf(v) - 1.f);     // ELU
            if (round_out) v = f2tf32f(v);
            o[c] = v;
        }
        float4* op = (float4*)(hout + (size_t)gw * DD + h * 16);
#pragma unroll
        for (int c = 0; c < 4; c++)
            op[c] = make_float4(o[4 * c], o[4 * c + 1], o[4 * c + 2], o[4 * c + 3]);
    }
}

// ---------------- global mean pool ----------------
__global__ __launch_bounds__(128) void pool_kernel(const int* __restrict__ batch) {
    int ch = threadIdx.x;
    int n0 = blockIdx.x * 128;
    int nEnd = n0 + 128; if (nEnd > NN) nEnd = NN;
    if (n0 >= NN) return;

    int cur = batch[n0];
    float acc = 0.f;
    int runlen = 0;
    for (int nd = n0; nd < nEnd; nd++) {
        int gidx = batch[nd];
        if (gidx != cur) {
            atomicAdd(&g_pool[cur * DD + ch], acc);
            if (ch == 0) atomicAdd(&g_pcnt[cur], (float)runlen);
            acc = 0.f; runlen = 0; cur = gidx;
        }
        acc += g_bufA[(size_t)nd * DD + ch];
        runlen++;
    }
    atomicAdd(&g_pool[cur * DD + ch], acc);
    if (ch == 0) atomicAdd(&g_pcnt[cur], (float)runlen);
}

// ---------------- classifier + log_softmax ----------------
__global__ void cls_kernel(const float* __restrict__ Wout,
                           const float* __restrict__ bout,
                           float* __restrict__ out) {
    __shared__ float slog[NG][NC];
    __shared__ float srow[NG];
    int t = threadIdx.x;
    if (t < NG * NC) {
        int g = t / NC, c = t % NC;
        float inv = 1.f / fmaxf(g_pcnt[g], 1.f);
        float acc = 0.f;
        for (int k = 0; k < DD; k++) acc += g_pool[g * DD + k] * Wout[k * NC + c];
        slog[g][c] = acc * inv + bout[c];
    }
    __syncthreads();
    if (t < NG) {
        float mx = -3.0e38f;
        for (int c = 0; c < NC; c++) mx = fmaxf(mx, slog[t][c]);
        float ssum = 0.f;
        for (int c = 0; c < NC; c++) ssum += expf(slog[t][c] - mx);
        srow[t] = mx + logf(ssum);
    }
    __syncthreads();
    if (t < NG * NC) out[t] = slog[t / NC][t % NC] - srow[t / NC];
}

// ---------------- driver ----------------
extern "C" void kernel_launch(void* const* d_in, const int* in_sizes, int n_in,
                              void* d_out, int out_size) {
    const float* x     = (const float*)d_in[0];
    const int*   ei    = (const int*)  d_in[1];
    const int*   batch = (const int*)  d_in[2];
    const float* Wl    = (const float*)d_in[3];
    const float* bl    = (const float*)d_in[4];
    const float* Wr    = (const float*)d_in[5];
    const float* br    = (const float*)d_in[6];
    const float* att   = (const float*)d_in[7];
    const float* bias  = (const float*)d_in[8];
    const float* Wout  = (const float*)d_in[9];
    const float* bout  = (const float*)d_in[10];
    float* out = (float*)d_out;

    dim3 ggrid((NN + GBM - 1) / GBM, 4);

    // launch #3 (0-based) = layer-0 GEMM for ncu capture
    init_kernel<<<(NN + 255) / 256, 256>>>();
    pack_kernel<<<(NL * DD * 256 + NL * 256 + 255) / 256, 256>>>(Wl, bl, Wr, br);
    roundx_kernel<<<(NN * DD / 4 + 255) / 256, 256>>>(x);
    gemm_tc_kernel<<<ggrid, 256>>>(0);

    count_kernel<<<(NE + 255) / 256, 256>>>(ei);
    scan1_kernel<<<SCAN_BLOCKS, 1024>>>();
    scan2_kernel<<<1, 32>>>();
    scan3_kernel<<<SCAN_BLOCKS, 1024>>>();
    scatter_kernel<<<(NE + 255) / 256, 256>>>(ei);

    for (int l = 0; l < NL; l++) {
        if (l > 0) gemm_tc_kernel<<<ggrid, 256>>>(l);
        int outbuf = (l % 2 == 0) ? 0 : 1;
        int round_out = (l < NL - 1) ? 1 : 0;
        gat_kernel<<<(NN * 32 + 255) / 256, 256>>>(att + l * DD, bias + l * DD, outbuf, round_out);
    }

    pool_kernel<<<(NN + 127) / 128, 128>>>(batch);
    cls_kernel<<<1, 640>>>(Wout, bout, out);
}

// round 11
// speedup vs baseline: 1.6952x; 1.1796x over previous
#include <cuda_runtime.h>
#include <cuda_fp16.h>
#include <cstdint>

#define NN 50000
#define NE_IN 800000
#define NE (NE_IN + NN)
#define DD 128
#define NG 64
#define NC 10
#define NL 5

#define SCAN_BLOCKS ((NN + 1023) / 1024)

// ---------------- static device scratch ----------------
__device__ __align__(16) __half g_bufA[NN * DD];     // h buffers now fp16
__device__ __align__(16) __half g_bufB[NN * DD];
__device__ __align__(16) __half g_xlh[NN * DD];      // fp16 xl (message/logit source)
__device__ __align__(16) float  g_xr[NN * DD];       // xr stays fp32 (coalesced per-node read)
__device__ __align__(16) __half g_WpackH[NL * 256 * DD];  // transposed: [l][n(0..255)][k(0..127)]
__device__ __align__(16) float  g_bpack[NL * 256];
__device__ int   g_rowptr[NN + 1];
__device__ int   g_cursor[NN];
__device__ int   g_esrc[NE];
__device__ int   g_cnt[NN];
__device__ int   g_bsum[64];
__device__ __align__(16) float g_pool[NG * DD];
__device__ float g_pcnt[NG];

// ---------------- init ----------------
__global__ void init_kernel() {
    int i = blockIdx.x * blockDim.x + threadIdx.x;
    if (i < NN) g_cnt[i] = 0;
    if (i < NG * DD) g_pool[i] = 0.f;
    if (i < NG) g_pcnt[i] = 0.f;
}

// ---------------- convert x (layer-0 input) into g_bufB as fp16 ----------------
__global__ void roundx_kernel(const float* __restrict__ x) {
    int i = blockIdx.x * blockDim.x + threadIdx.x;
    if (i < NN * DD / 4) {
        float4 v = ((const float4*)x)[i];
        __half2 h0 = __floats2half2_rn(v.x, v.y);
        __half2 h1 = __floats2half2_rn(v.z, v.w);
        ((__half2*)g_bufB)[2 * i]     = h0;
        ((__half2*)g_bufB)[2 * i + 1] = h1;
    }
}

// ---------------- CSR build ----------------
__global__ void count_kernel(const int* __restrict__ ei) {
    int e = blockIdx.x * blockDim.x + threadIdx.x;
    if (e >= NE) return;
    int d = (e < NE_IN) ? ei[NE_IN + e] : (e - NE_IN);
    atomicAdd(&g_cnt[d], 1);
}

__global__ void scan1_kernel() {
    __shared__ int wsum[32];
    int tid = threadIdx.x;
    int i = blockIdx.x * 1024 + tid;
    int v = (i < NN) ? g_cnt[i] : 0;
    int x = v;
#pragma unroll
    for (int off = 1; off < 32; off <<= 1) {
        int y = __shfl_up_sync(0xffffffffu, x, off);
        if ((tid & 31) >= off) x += y;
    }
    if ((tid & 31) == 31) wsum[tid >> 5] = x;
    __syncthreads();
    if (tid < 32) {
        int w = wsum[tid];
        int xs = w;
#pragma unroll
        for (int off = 1; off < 32; off <<= 1) {
            int y = __shfl_up_sync(0xffffffffu, xs, off);
            if (tid >= off) xs += y;
        }
        wsum[tid] = xs - w;
    }
    __syncthreads();
    int incl = x + wsum[tid >> 5];
    if (i < NN) g_rowptr[i] = incl - v;
    if (tid == 1023) g_bsum[blockIdx.x] = incl;
}

__global__ void scan2_kernel() {
    if (threadIdx.x == 0) {
        int acc = 0;
        for (int b = 0; b < SCAN_BLOCKS; b++) { int t = g_bsum[b]; g_bsum[b] = acc; acc += t; }
    }
}

__global__ void scan3_kernel() {
    int i = blockIdx.x * 1024 + threadIdx.x;
    if (i < NN) {
        int r = g_rowptr[i] + g_bsum[blockIdx.x];
        g_rowptr[i] = r;
        g_cursor[i] = r;
    }
    if (i == 0) g_rowptr[NN] = NE;
}

__global__ void scatter_kernel(const int* __restrict__ ei) {
    int e = blockIdx.x * blockDim.x + threadIdx.x;
    if (e >= NE) return;
    int s, d;
    if (e < NE_IN) { s = ei[e]; d = ei[NE_IN + e]; }
    else           { s = e - NE_IN; d = s; }
    int pos = atomicAdd(&g_cursor[d], 1);
    g_esrc[pos] = s;
}

// ---------------- pack weights: fp16, TRANSPOSED [l][n][k] ----------------
__global__ void pack_kernel(const float* __restrict__ Wl, const float* __restrict__ bl,
                            const float* __restrict__ Wr, const float* __restrict__ br) {
    int i = blockIdx.x * blockDim.x + threadIdx.x;
    int WTOT = NL * 256 * DD;
    if (i < WTOT) {
        int l = i / (256 * DD);
        int rem = i - l * 256 * DD;
        int n = rem >> 7, k = rem & 127;      // n = output col, k = input row
        float w = (n < DD) ? Wl[(l * DD + k) * DD + n]
                           : Wr[(l * DD + k) * DD + (n - DD)];
        g_WpackH[i] = __float2half_rn(w);
    } else if (i < WTOT + NL * 256) {
        int r = i - WTOT;
        int l = r >> 8, j = r & 255;
        g_bpack[r] = (j < DD) ? bl[l * DD + j] : br[l * DD + j - DD];
    }
}

// ---------------- fp16 tensor-core GEMM, m16n8k16, BK=32, 2-stage ----------------
#define GBM 128
#define GBN 64
#define GBK 32
#define NKT (DD / GBK)   // 4
#define APAD 40          // halves per A row in smem (conflict-free)
#define BPAD 40

__device__ __forceinline__ void cpa16(void* smem, const void* g) {
    unsigned sa = (unsigned)__cvta_generic_to_shared(smem);
    asm volatile("cp.async.cg.shared.global [%0], [%1], 16;" :: "r"(sa), "l"(g));
}
__device__ __forceinline__ void mma16h(float* c, const uint32_t* a, const uint32_t* b) {
    asm volatile(
        "mma.sync.aligned.m16n8k16.row.col.f32.f16.f16.f32 "
        "{%0,%1,%2,%3},{%4,%5,%6,%7},{%8,%9},{%0,%1,%2,%3};"
        : "+f"(c[0]), "+f"(c[1]), "+f"(c[2]), "+f"(c[3])
        : "r"(a[0]), "r"(a[1]), "r"(a[2]), "r"(a[3]), "r"(b[0]), "r"(b[1]));
}

__global__ __launch_bounds__(256) void gemm_tc_kernel(int l) {
    const __half* A = (l & 1) ? g_bufA : g_bufB;   // l=0 reads x in bufB
    __shared__ __half As[2][GBM][APAD];   // 128 x 40 halves
    __shared__ __half Bs[2][GBN][BPAD];   // 64 x 40 halves (row = n, col = k)

    int tid  = threadIdx.x;
    int lane = tid & 31;
    int warp = tid >> 5;
    int wm = warp >> 1, wn = warp & 1;
    int g = lane >> 2, t = lane & 3;
    int bm0 = blockIdx.x * GBM;

    const __half* WbT = g_WpackH + l * (256 * DD) + (size_t)(blockIdx.y * GBN) * DD;

    float acc[2][4][4];
#pragma unroll
    for (int mt = 0; mt < 2; mt++)
#pragma unroll
        for (int nt = 0; nt < 4; nt++)
#pragma unroll
            for (int c = 0; c < 4; c++) acc[mt][nt][c] = 0.f;

    auto load_stage = [&](int buf, int k0) {
        // A: 128 rows x 32 halves = 512 16B-chunks -> 2 per thread
#pragma unroll
        for (int i = 0; i < 2; i++) {
            int idx = tid + i * 256;
            int row = idx >> 2, q = idx & 3;       // 4 chunks (8 halves each) per row
            int gr = bm0 + row; if (gr >= NN) gr = NN - 1;
            cpa16(&As[buf][row][q * 8], A + (size_t)gr * DD + k0 + q * 8);
        }
        // B: 64 rows(n) x 32 halves(k) = 256 chunks -> 1 per thread
        {
            int row = tid >> 2, q = tid & 3;
            cpa16(&Bs[buf][row][q * 8], WbT + (size_t)row * DD + k0 + q * 8);
        }
        asm volatile("cp.async.commit_group;");
    };

    load_stage(0, 0);

    int buf = 0;
#pragma unroll
    for (int kt = 0; kt < NKT; kt++) {
        if (kt + 1 < NKT) {
            load_stage(buf ^ 1, (kt + 1) * GBK);
            asm volatile("cp.async.wait_group 1;");
        } else {
            asm volatile("cp.async.wait_group 0;");
        }
        __syncthreads();

#pragma unroll
        for (int ks = 0; ks < 2; ks++) {
            int kk = ks * 16;
            uint32_t af[2][4];
#pragma unroll
            for (int mt = 0; mt < 2; mt++) {
                int r0 = wm * 32 + mt * 16 + g;
                af[mt][0] = *(const uint32_t*)&As[buf][r0][kk + 2 * t];
                af[mt][1] = *(const uint32_t*)&As[buf][r0 + 8][kk + 2 * t];
                af[mt][2] = *(const uint32_t*)&As[buf][r0][kk + 2 * t + 8];
                af[mt][3] = *(const uint32_t*)&As[buf][r0 + 8][kk + 2 * t + 8];
            }
            uint32_t bf[4][2];
#pragma unroll
            for (int nt = 0; nt < 4; nt++) {
                int c0 = wn * 32 + nt * 8 + g;
                bf[nt][0] = *(const uint32_t*)&Bs[buf][c0][kk + 2 * t];
                bf[nt][1] = *(const uint32_t*)&Bs[buf][c0][kk + 2 * t + 8];
            }
#pragma unroll
            for (int mt = 0; mt < 2; mt++)
#pragma unroll
                for (int nt = 0; nt < 4; nt++)
                    mma16h(acc[mt][nt], af[mt], bf[nt]);
        }
        __syncthreads();
        buf ^= 1;
    }

    // epilogue: cols [0,128) -> g_xlh (fp16), cols [128,256) -> g_xr (fp32)
    int cbase = blockIdx.y * GBN + wn * 32;
    const float* bp = g_bpack + l * 256;
    bool isXL = (blockIdx.y < 2);
    int coff = isXL ? cbase : cbase - DD;
#pragma unroll
    for (int mt = 0; mt < 2; mt++) {
        int r0 = bm0 + wm * 32 + mt * 16 + g;
#pragma unroll
        for (int nt = 0; nt < 4; nt++) {
            int cb = cbase + nt * 8 + 2 * t;
            int c  = coff + nt * 8 + 2 * t;
            float bx = bp[cb], by = bp[cb + 1];
            if (r0 < NN) {
                float vx = acc[mt][nt][0] + bx, vy = acc[mt][nt][1] + by;
                if (isXL) *(__half2*)(g_xlh + (size_t)r0 * DD + c) = __floats2half2_rn(vx, vy);
                else      *(float2*)(g_xr + (size_t)r0 * DD + c) = make_float2(vx, vy);
            }
            if (r0 + 8 < NN) {
                float vx = acc[mt][nt][2] + bx, vy = acc[mt][nt][3] + by;
                if (isXL) *(__half2*)(g_xlh + (size_t)(r0 + 8) * DD + c) = __floats2half2_rn(vx, vy);
                else      *(float2*)(g_xr + (size_t)(r0 + 8) * DD + c) = make_float2(vx, vy);
            }
        }
    }
}

// ---------------- GAT edge aggregation (fp16 gathers, data-prefetch pipelined) ----------------
__device__ __forceinline__ float lrl(float z) { return z > 0.f ? z : 0.2f * z; }

__global__ __launch_bounds__(256) void gat_kernel(const float* __restrict__ attb,
                                                  const float* __restrict__ biasb,
                                                  int outbuf) {
    int gw = (blockIdx.x * blockDim.x + threadIdx.x) >> 5;
    int lane = threadIdx.x & 31;
    if (gw >= NN) return;
    __half* hout = (outbuf == 0) ? g_bufA : g_bufB;

    int slot = lane >> 3, h = lane & 7;

    float at[16], xr[16], ac[16];
#pragma unroll
    for (int c = 0; c < 4; c++) {
        float4 a4 = ((const float4*)(attb + h * 16))[c];
        at[4 * c + 0] = a4.x; at[4 * c + 1] = a4.y; at[4 * c + 2] = a4.z; at[4 * c + 3] = a4.w;
        float4 r4 = ((const float4*)(g_xr + (size_t)gw * DD + h * 16))[c];
        xr[4 * c + 0] = r4.x; xr[4 * c + 1] = r4.y; xr[4 * c + 2] = r4.z; xr[4 * c + 3] = r4.w;
    }
#pragma unroll
    for (int c = 0; c < 16; c++) ac[c] = 0.f;

    int jb = g_rowptr[gw], je = g_rowptr[gw + 1];
    float s = 0.f;

    int jbase = jb + slot;
    int nIter = (je - jb + 3) >> 2;

    // prologue: data for iter 0 + index for iter 1
    int src0 = __ldg(&g_esrc[jbase < je ? jbase : je - 1]);
    const uint4* lp0 = (const uint4*)(g_xlh + (size_t)src0 * DD + h * 16);
    uint4 u0 = __ldg(lp0), u1 = __ldg(lp0 + 1);
    int jn = jbase + 4;
    int srcn = __ldg(&g_esrc[jn < je ? jn : je - 1]);

    for (int it = 0; it < nIter; it++) {
        // prefetch next iteration's data, then next-next index
        const uint4* lpn = (const uint4*)(g_xlh + (size_t)srcn * DD + h * 16);
        uint4 v0 = __ldg(lpn), v1 = __ldg(lpn + 1);
        jn += 4;
        srcn = __ldg(&g_esrc[jn < je ? jn : je - 1]);

        bool act = (jbase + 4 * it < je);

        float xs[16];
        {
            const __half2* hh0 = (const __half2*)&u0;
            const __half2* hh1 = (const __half2*)&u1;
#pragma unroll
            for (int k = 0; k < 4; k++) {
                float2 f = __half22float2(hh0[k]);
                xs[2 * k] = f.x; xs[2 * k + 1] = f.y;
            }
#pragma unroll
            for (int k = 0; k < 4; k++) {
                float2 f = __half22float2(hh1[k]);
                xs[8 + 2 * k] = f.x; xs[8 + 2 * k + 1] = f.y;
            }
        }

        float d = 0.f;
#pragma unroll
        for (int c = 0; c < 16; c++) d += at[c] * lrl(xs[c] + xr[c]);

        float p = act ? __expf(d) : 0.f;
        s += p;
#pragma unroll
        for (int c = 0; c < 16; c++) ac[c] += p * xs[c];

        u0 = v0; u1 = v1;
    }

    // merge 4 slots
#pragma unroll
    for (int off = 8; off <= 16; off <<= 1) {
        s += __shfl_xor_sync(0xffffffffu, s, off);
#pragma unroll
        for (int c = 0; c < 16; c++) ac[c] += __shfl_xor_sync(0xffffffffu, ac[c], off);
    }

    if (slot == 0) {
        float inv = 1.f / s;
        __half2 oh[8];
#pragma unroll
        for (int c = 0; c < 4; c++) {
            float4 b4 = ((const float4*)(biasb + h * 16))[c];
            float o0 = ac[4 * c + 0] * inv + b4.x;
            float o1 = ac[4 * c + 1] * inv + b4.y;
            float o2 = ac[4 * c + 2] * inv + b4.z;
            float o3 = ac[4 * c + 3] * inv + b4.w;
            o0 = o0 > 0.f ? o0 : (__expf(o0) - 1.f);
            o1 = o1 > 0.f ? o1 : (__expf(o1) - 1.f);
            o2 = o2 > 0.f ? o2 : (__expf(o2) - 1.f);
            o3 = o3 > 0.f ? o3 : (__expf(o3) - 1.f);
            oh[2 * c]     = __floats2half2_rn(o0, o1);
            oh[2 * c + 1] = __floats2half2_rn(o2, o3);
        }
        uint4* op = (uint4*)(hout + (size_t)gw * DD + h * 16);
        op[0] = *(uint4*)&oh[0];
        op[1] = *(uint4*)&oh[4];
    }
}

// ---------------- global mean pool (reads fp16 h) ----------------
__global__ __launch_bounds__(128) void pool_kernel(const int* __restrict__ batch) {
    int ch = threadIdx.x;
    int n0 = blockIdx.x * 128;
    int nEnd = n0 + 128; if (nEnd > NN) nEnd = NN;
    if (n0 >= NN) return;

    int cur = batch[n0];
    float acc = 0.f;
    int runlen = 0;
    for (int nd = n0; nd < nEnd; nd++) {
        int gidx = batch[nd];
        if (gidx != cur) {
            atomicAdd(&g_pool[cur * DD + ch], acc);
            if (ch == 0) atomicAdd(&g_pcnt[cur], (float)runlen);
            acc = 0.f; runlen = 0; cur = gidx;
        }
        acc += __half2float(g_bufA[(size_t)nd * DD + ch]);
        runlen++;
    }
    atomicAdd(&g_pool[cur * DD + ch], acc);
    if (ch == 0) atomicAdd(&g_pcnt[cur], (float)runlen);
}

// ---------------- classifier + log_softmax ----------------
__global__ void cls_kernel(const float* __restrict__ Wout,
                           const float* __restrict__ bout,
                           float* __restrict__ out) {
    __shared__ float slog[NG][NC];
    __shared__ float srow[NG];
    int t = threadIdx.x;
    if (t < NG * NC) {
        int g = t / NC, c = t % NC;
        float inv = 1.f / fmaxf(g_pcnt[g], 1.f);
        float acc = 0.f;
        for (int k = 0; k < DD; k++) acc += g_pool[g * DD + k] * Wout[k * NC + c];
        slog[g][c] = acc * inv + bout[c];
    }
    __syncthreads();
    if (t < NG) {
        float mx = -3.0e38f;
        for (int c = 0; c < NC; c++) mx = fmaxf(mx, slog[t][c]);
        float ssum = 0.f;
        for (int c = 0; c < NC; c++) ssum += expf(slog[t][c] - mx);
        srow[t] = mx + logf(ssum);
    }
    __syncthreads();
    if (t < NG * NC) out[t] = slog[t / NC][t % NC] - srow[t / NC];
}

// ---------------- driver ----------------
extern "C" void kernel_launch(void* const* d_in, const int* in_sizes, int n_in,
                              void* d_out, int out_size) {
    const float* x     = (const float*)d_in[0];
    const int*   ei    = (const int*)  d_in[1];
    const int*   batch = (const int*)  d_in[2];
    const float* Wl    = (const float*)d_in[3];
    const float* bl    = (const float*)d_in[4];
    const float* Wr    = (const float*)d_in[5];
    const float* br    = (const float*)d_in[6];
    const float* att   = (const float*)d_in[7];
    const float* bias  = (const float*)d_in[8];
    const float* Wout  = (const float*)d_in[9];
    const float* bout  = (const float*)d_in[10];
    float* out = (float*)d_out;

    dim3 ggrid((NN + GBM - 1) / GBM, 4);

    // launch #3 (0-based) = layer-0 GEMM for ncu capture
    init_kernel<<<(NN + 255) / 256, 256>>>();
    pack_kernel<<<(NL * 256 * DD + NL * 256 + 255) / 256, 256>>>(Wl, bl, Wr, br);
    roundx_kernel<<<(NN * DD / 4 + 255) / 256, 256>>>(x);
    gemm_tc_kernel<<<ggrid, 256>>>(0);

    count_kernel<<<(NE + 255) / 256, 256>>>(ei);
    scan1_kernel<<<SCAN_BLOCKS, 1024>>>();
    scan2_kernel<<<1, 32>>>();
    scan3_kernel<<<SCAN_BLOCKS, 1024>>>();
    scatter_kernel<<<(NE + 255) / 256, 256>>>(ei);

    for (int l = 0; l < NL; l++) {
        if (l > 0) gemm_tc_kernel<<<ggrid, 256>>>(l);
        int outbuf = (l % 2 == 0) ? 0 : 1;
        gat_kernel<<<(NN * 32 + 255) / 256, 256>>>(att + l * DD, bias + l * DD, outbuf);
    }

    pool_kernel<<<(NN + 127) / 128, 128>>>(batch);
    cls_kernel<<<1, 640>>>(Wout, bout, out);
}